// round 3
// baseline (speedup 1.0000x reference)
#include <cuda_runtime.h>
#include <math.h>

#define Bq 16
#define Sq 2048
#define Hq 512
#define Oq 16
#define BSq (Bq*Sq)            // 32768
#define RSQRT_H 0.04419417382415922f   // 1/sqrt(512)

typedef unsigned long long ull;

__device__ __forceinline__ ull ffma2(ull a, ull b, ull c) {
    ull d; asm("fma.rn.f32x2 %0, %1, %2, %3;" : "=l"(d) : "l"(a), "l"(b), "l"(c));
    return d;
}
__device__ __forceinline__ ull addf2(ull a, ull b) {
    ull d; asm("add.rn.f32x2 %0, %1, %2;" : "=l"(d) : "l"(a), "l"(b));
    return d;
}
__device__ __forceinline__ ull dup2(float f) {
    ull r; asm("mov.b64 %0, {%1, %1};" : "=l"(r) : "f"(f));
    return r;
}

// ---------------- scratch (device globals) ----------------------------------
__device__ float g_oq[Oq*Hq];          // raw operator queries (atomic accum)
__device__ float g_kqT[Hq*Oq];         // transposed kq [k][o], pre-scaled
__device__ float g_c[Oq];              // bk . oq, pre-scaled
__device__ float g_logits[BSq*Oq];     // [b][s][o]
__device__ float g_esum[Bq*Oq];        // sum_s exp(logits)  (atomic)
__device__ float g_W[Bq*Oq];           // sum_s w            (atomic, unnormalized)
__device__ float g_u[Bq*Oq*Hq];        // sum_s w * x        (atomic, unnormalized)
__device__ float g_opout[Bq*Oq*Hq];    // operator outputs

// ---------------- K-zero -----------------------------------------------------
__global__ void kzero() {
    int i = blockIdx.x * 256 + threadIdx.x;
    if (i < Bq*Oq*Hq) g_u[i] = 0.f;
    if (i < Oq*Hq)    g_oq[i] = 0.f;
    if (i < Bq*Oq)    { g_esum[i] = 0.f; g_W[i] = 0.f; }
}

// ---------------- K0a: oq[o][h] = sum_s ops[s][o] * Wq_op[h][s] --------------
__global__ void __launch_bounds__(512) k0a(const float* __restrict__ Wq_op,
                                           const float* __restrict__ ops) {
    __shared__ float ops_sh[128*16];
    __shared__ float wq_sh[64][129];
    int h0 = blockIdx.x * 64, s0 = blockIdx.y * 128;
    for (int i = threadIdx.x; i < 128*16; i += 512)
        ops_sh[i] = ops[s0*16 + i];
    for (int i = threadIdx.x; i < 64*128; i += 512) {
        int r = i >> 7, c = i & 127;
        wq_sh[r][c] = Wq_op[(size_t)(h0 + r)*Sq + s0 + c];
    }
    __syncthreads();
    int hl = threadIdx.x & 63;
    int og = threadIdx.x >> 6;
    float a0 = 0.f, a1 = 0.f;
    #pragma unroll 8
    for (int s = 0; s < 128; s++) {
        float wv = wq_sh[hl][s];
        a0 += wv * ops_sh[s*16 + og*2];
        a1 += wv * ops_sh[s*16 + og*2 + 1];
    }
    atomicAdd(&g_oq[(og*2    )*Hq + h0 + hl], a0);
    atomicAdd(&g_oq[(og*2 + 1)*Hq + h0 + hl], a1);
}

// ---------------- K0b: kqT[k][o] = (oq+bq)@Wk * rsqrtH; c = bk.(oq+bq)*rs ---
__global__ void __launch_bounds__(128) k0b(const float* __restrict__ Wk,
                                           const float* __restrict__ bk,
                                           const float* __restrict__ bq,
                                           float* oq_out) {
    __shared__ float oq_sh[Hq];
    __shared__ float cr[128];
    int o = blockIdx.x, kc = blockIdx.y;
    for (int h = threadIdx.x; h < Hq; h += 128) {
        float v = g_oq[o*Hq + h] + bq[h];
        oq_sh[h] = v;
        if (kc == 0 && oq_out) oq_out[o*Hq + h] = v;
    }
    __syncthreads();
    int k = kc*128 + threadIdx.x;
    float a = 0.f;
    #pragma unroll 16
    for (int h = 0; h < Hq; h++)
        a += oq_sh[h] * Wk[(size_t)h*Hq + k];
    g_kqT[k*16 + o] = a * RSQRT_H;
    if (kc == 0) {
        float cl = 0.f;
        for (int h = threadIdx.x; h < Hq; h += 128) cl += bk[h] * oq_sh[h];
        cr[threadIdx.x] = cl;
        __syncthreads();
        for (int st = 64; st > 0; st >>= 1) {
            if (threadIdx.x < st) cr[threadIdx.x] += cr[threadIdx.x + st];
            __syncthreads();
        }
        if (threadIdx.x == 0) g_c[o] = cr[0] * RSQRT_H;
    }
}

// ---------------- helpers for kA ---------------------------------------------
__device__ __forceinline__ void melem(const float* kp,
                                      float e0, float e1, float e2, float e3,
                                      ull acc[4][8]) {
    ulonglong2 k0 = ((const ulonglong2*)kp)[0];
    ulonglong2 k1 = ((const ulonglong2*)kp)[1];
    ulonglong2 k2 = ((const ulonglong2*)kp)[2];
    ulonglong2 k3 = ((const ulonglong2*)kp)[3];
    ull a;
    a = dup2(e0);
    acc[0][0]=ffma2(a,k0.x,acc[0][0]); acc[0][1]=ffma2(a,k0.y,acc[0][1]);
    acc[0][2]=ffma2(a,k1.x,acc[0][2]); acc[0][3]=ffma2(a,k1.y,acc[0][3]);
    acc[0][4]=ffma2(a,k2.x,acc[0][4]); acc[0][5]=ffma2(a,k2.y,acc[0][5]);
    acc[0][6]=ffma2(a,k3.x,acc[0][6]); acc[0][7]=ffma2(a,k3.y,acc[0][7]);
    a = dup2(e1);
    acc[1][0]=ffma2(a,k0.x,acc[1][0]); acc[1][1]=ffma2(a,k0.y,acc[1][1]);
    acc[1][2]=ffma2(a,k1.x,acc[1][2]); acc[1][3]=ffma2(a,k1.y,acc[1][3]);
    acc[1][4]=ffma2(a,k2.x,acc[1][4]); acc[1][5]=ffma2(a,k2.y,acc[1][5]);
    acc[1][6]=ffma2(a,k3.x,acc[1][6]); acc[1][7]=ffma2(a,k3.y,acc[1][7]);
    a = dup2(e2);
    acc[2][0]=ffma2(a,k0.x,acc[2][0]); acc[2][1]=ffma2(a,k0.y,acc[2][1]);
    acc[2][2]=ffma2(a,k1.x,acc[2][2]); acc[2][3]=ffma2(a,k1.y,acc[2][3]);
    acc[2][4]=ffma2(a,k2.x,acc[2][4]); acc[2][5]=ffma2(a,k2.y,acc[2][5]);
    acc[2][6]=ffma2(a,k3.x,acc[2][6]); acc[2][7]=ffma2(a,k3.y,acc[2][7]);
    a = dup2(e3);
    acc[3][0]=ffma2(a,k0.x,acc[3][0]); acc[3][1]=ffma2(a,k0.y,acc[3][1]);
    acc[3][2]=ffma2(a,k1.x,acc[3][2]); acc[3][3]=ffma2(a,k1.y,acc[3][3]);
    acc[3][4]=ffma2(a,k2.x,acc[3][4]); acc[3][5]=ffma2(a,k2.y,acc[3][5]);
    acc[3][6]=ffma2(a,k3.x,acc[3][6]); acc[3][7]=ffma2(a,k3.y,acc[3][7]);
}

// fold-reduce 8 ull (f32x2 pairs) over 32 lanes; after: lane l holds pair
// index p = (l>>1)&7 in v[0] (lanes with l&1==0, l<16 are canonical writers)
__device__ __forceinline__ void fold8(ull v[8], int lane) {
    #pragma unroll
    for (int i = 0; i < 8; i++)
        v[i] = addf2(v[i], __shfl_xor_sync(0xffffffffu, v[i], 16));
    #pragma unroll
    for (int i = 0; i < 4; i++) {
        ull mn = (lane & 8) ? v[i+4] : v[i];
        ull th = (lane & 8) ? v[i] : v[i+4];
        v[i] = addf2(mn, __shfl_xor_sync(0xffffffffu, th, 8));
    }
    #pragma unroll
    for (int i = 0; i < 2; i++) {
        ull mn = (lane & 4) ? v[i+2] : v[i];
        ull th = (lane & 4) ? v[i] : v[i+2];
        v[i] = addf2(mn, __shfl_xor_sync(0xffffffffu, th, 4));
    }
    {
        ull mn = (lane & 2) ? v[1] : v[0];
        ull th = (lane & 2) ? v[0] : v[1];
        v[0] = addf2(mn, __shfl_xor_sync(0xffffffffu, th, 2));
    }
    v[0] = addf2(v[0], __shfl_xor_sync(0xffffffffu, v[0], 1));
}

// ---------------- kA: fused logits + exp-sums + unnormalized u ---------------
// grid 1024 (32 rows each), 256 threads
__global__ void __launch_bounds__(256) kA(const float* __restrict__ x,
                                          const float* __restrict__ ops) {
    __shared__ __align__(16) float kq_sh[Hq*16];   // 32KB [k][o]
    __shared__ float c_sh[16];
    __shared__ __align__(16) ull  st2[32*8];       // raw logits [row][opair]
    __shared__ __align__(16) float w_sh[32*16];    // unnormalized weights
    __shared__ float esr[16][17];
    __shared__ float wsr[16][17];
    int tid = threadIdx.x;
    for (int i = tid; i < Hq*16/4; i += 256)
        ((float4*)kq_sh)[i] = ((const float4*)g_kqT)[i];
    if (tid < 16) c_sh[tid] = g_c[tid];
    __syncthreads();

    int wid = tid >> 5, lane = tid & 31;
    int b = blockIdx.x >> 6;
    int row0 = blockIdx.x * 32;            // global row
    int s0 = (blockIdx.x & 63) * 32;       // s within batch

    // phase 1: logits for this warp's 4 rows (FFMA2, o-pairs)
    {
        int r0 = row0 + wid * 4;
        const float4* xr = ((const float4*)x) + (size_t)r0 * 128;
        ull acc[4][8];
        #pragma unroll
        for (int r = 0; r < 4; r++)
            #pragma unroll
            for (int p = 0; p < 8; p++) acc[r][p] = 0ull;
        #pragma unroll
        for (int jj = 0; jj < 4; jj++) {
            int j = jj * 32 + lane;
            float4 x0 = xr[j], x1 = xr[128 + j], x2 = xr[256 + j], x3 = xr[384 + j];
            const float* kp = kq_sh + (size_t)(4*j) * 16;
            melem(kp,      x0.x, x1.x, x2.x, x3.x, acc);
            melem(kp + 16, x0.y, x1.y, x2.y, x3.y, acc);
            melem(kp + 32, x0.z, x1.z, x2.z, x3.z, acc);
            melem(kp + 48, x0.w, x1.w, x2.w, x3.w, acc);
        }
        #pragma unroll
        for (int r = 0; r < 4; r++) {
            fold8(acc[r], lane);
            if (lane < 16 && !(lane & 1))
                st2[(wid*4 + r)*8 + ((lane >> 1) & 7)] = acc[r][0];
        }
    }
    __syncthreads();

    // phase 1.5: +c, store logits, build w = exp(L)*ops, partial sums
    const float* stf = (const float*)st2;
    float v0 = stf[tid]       + c_sh[tid & 15];
    float v1 = stf[tid + 256] + c_sh[tid & 15];
    size_t gb = (size_t)blockIdx.x * 512;
    g_logits[gb + tid]       = v0;
    g_logits[gb + tid + 256] = v1;
    float e0 = __expf(v0), e1 = __expf(v1);
    const float* opb = ops + (size_t)s0 * 16;
    float w0 = e0 * opb[tid], w1 = e1 * opb[tid + 256];
    w_sh[tid]       = w0;
    w_sh[tid + 256] = w1;
    esr[tid >> 4][tid & 15] = e0 + e1;
    wsr[tid >> 4][tid & 15] = w0 + w1;
    __syncthreads();
    if (tid < 16) {
        float se = 0.f, sw = 0.f;
        #pragma unroll
        for (int j = 0; j < 16; j++) { se += esr[j][tid]; sw += wsr[j][tid]; }
        atomicAdd(&g_esum[b*16 + tid], se);
        atomicAdd(&g_W[b*16 + tid], sw);
    }

    // phase 2: u[b,o,k] += sum_{s in tile} w[s,o] * x[s,k]   (x is L1-hot)
    {
        const float* xq = x + (size_t)row0 * 512 + tid;
        ull a0[8], a1[8];
        #pragma unroll
        for (int j = 0; j < 8; j++) { a0[j] = 0ull; a1[j] = 0ull; }
        #pragma unroll 8
        for (int s = 0; s < 32; s++) {
            float xv0 = xq[(size_t)s * 512];
            float xv1 = xq[(size_t)s * 512 + 256];
            ull xa = dup2(xv0), xb = dup2(xv1);
            const ull* w8 = (const ull*)(w_sh + s*16);
            #pragma unroll
            for (int j = 0; j < 8; j++) {
                ull wv = w8[j];
                a0[j] = ffma2(xa, wv, a0[j]);
                a1[j] = ffma2(xb, wv, a1[j]);
            }
        }
        float* up = g_u + (size_t)b * 16 * 512;
        #pragma unroll
        for (int j = 0; j < 8; j++) {
            float lo, hi;
            asm("mov.b64 {%0,%1}, %2;" : "=f"(lo), "=f"(hi) : "l"(a0[j]));
            atomicAdd(&up[(2*j)*512   + tid], lo);
            atomicAdd(&up[(2*j+1)*512 + tid], hi);
            asm("mov.b64 {%0,%1}, %2;" : "=f"(lo), "=f"(hi) : "l"(a1[j]));
            atomicAdd(&up[(2*j)*512   + tid + 256], lo);
            atomicAdd(&up[(2*j+1)*512 + tid + 256], hi);
        }
    }
}

// fold-reduce 16 floats over 32 lanes; lane l (<16) ends holding total of v[l]
__device__ __forceinline__ float fold16(float v[16], int lane) {
    #pragma unroll
    for (int i = 0; i < 16; i++)
        v[i] += __shfl_xor_sync(0xffffffffu, v[i], 16);
    #pragma unroll
    for (int i = 0; i < 8; i++) {
        float mn = (lane & 8) ? v[i+8] : v[i];
        float th = (lane & 8) ? v[i] : v[i+8];
        v[i] = mn + __shfl_xor_sync(0xffffffffu, th, 8);
    }
    #pragma unroll
    for (int i = 0; i < 4; i++) {
        float mn = (lane & 4) ? v[i+4] : v[i];
        float th = (lane & 4) ? v[i] : v[i+4];
        v[i] = mn + __shfl_xor_sync(0xffffffffu, th, 4);
    }
    #pragma unroll
    for (int i = 0; i < 2; i++) {
        float mn = (lane & 2) ? v[i+2] : v[i];
        float th = (lane & 2) ? v[i] : v[i+2];
        v[i] = mn + __shfl_xor_sync(0xffffffffu, th, 2);
    }
    {
        float mn = (lane & 1) ? v[1] : v[0];
        float th = (lane & 1) ? v[0] : v[1];
        v[0] = mn + __shfl_xor_sync(0xffffffffu, th, 1);
    }
    return v[0];
}

// ---------------- K3: op_out = (u @ Wv^T)*inv + bv*(W*inv) -------------------
__global__ void __launch_bounds__(128) k3(const float* __restrict__ Wv,
                                          const float* __restrict__ bv) {
    __shared__ float4 u4[16*128];
    __shared__ float inv_sh[16], Wn_sh[16];
    int o = blockIdx.x, hc = blockIdx.y;
    for (int i = threadIdx.x; i < 16*128; i += 128) {
        int b = i >> 7, k4 = i & 127;
        u4[i] = ((const float4*)g_u)[((size_t)b*16 + o)*128 + k4];
    }
    if (threadIdx.x < 16) {
        float iv = 1.0f / g_esum[threadIdx.x*16 + o];
        inv_sh[threadIdx.x] = iv;
        Wn_sh[threadIdx.x]  = g_W[threadIdx.x*16 + o] * iv;
    }
    __syncthreads();
    int wid = threadIdx.x >> 5, lane = threadIdx.x & 31;
    for (int q = 0; q < 2; q++) {
        int h = hc*32 + wid*8 + q*4;
        const float4* wv = ((const float4*)Wv) + (size_t)h * 128;
        float acc[4][16];
        #pragma unroll
        for (int r = 0; r < 4; r++)
            #pragma unroll
            for (int b = 0; b < 16; b++) acc[r][b] = 0.f;
        #pragma unroll
        for (int jj = 0; jj < 4; jj++) {
            int j = jj*32 + lane;
            float4 v0 = wv[j], v1 = wv[128+j], v2 = wv[256+j], v3 = wv[384+j];
            #pragma unroll
            for (int b = 0; b < 16; b++) {
                float4 uu = u4[b*128 + j];
                acc[0][b] += v0.x*uu.x + v0.y*uu.y + v0.z*uu.z + v0.w*uu.w;
                acc[1][b] += v1.x*uu.x + v1.y*uu.y + v1.z*uu.z + v1.w*uu.w;
                acc[2][b] += v2.x*uu.x + v2.y*uu.y + v2.z*uu.z + v2.w*uu.w;
                acc[3][b] += v3.x*uu.x + v3.y*uu.y + v3.z*uu.z + v3.w*uu.w;
            }
        }
        #pragma unroll
        for (int r = 0; r < 4; r++) {
            float t = fold16(acc[r], lane);
            if (lane < 16)
                g_opout[((size_t)lane*16 + o)*Hq + h + r] =
                    t * inv_sh[lane] + bv[h + r] * Wn_sh[lane];
        }
    }
}

// ---------------- K4: out[b,s,h] = sum_o softmax_o(L)[o]*op_out[b,o,h] ------
__global__ void __launch_bounds__(256) k4(float* __restrict__ out) {
    __shared__ __align__(16) float4 op4[16*128];
    int b = blockIdx.y, sc = blockIdx.x;
    for (int i = threadIdx.x; i < 16*128; i += 256)
        op4[i] = ((const float4*)g_opout)[(size_t)b*2048 + i];
    __syncthreads();
    int wid = threadIdx.x >> 5, lane = threadIdx.x & 31;
    for (int q = 0; q < 2; q++) {
        int s0 = sc*64 + wid*8 + q*4;
        size_t r0 = (size_t)b*Sq + s0;
        const float* lp = g_logits + (r0 + (lane & 3)) * 16;
        float e[16];
        float mx = -1e30f;
        #pragma unroll
        for (int o = 0; o < 16; o++) { e[o] = lp[o]; mx = fmaxf(mx, e[o]); }
        float sum = 0.f;
        #pragma unroll
        for (int o = 0; o < 16; o++) { e[o] = __expf(e[o] - mx); sum += e[o]; }
        float inv = 1.0f / sum;
        float ow0[16], ow1[16], ow2[16], ow3[16];
        #pragma unroll
        for (int o = 0; o < 16; o++) {
            float v = e[o] * inv;
            ow0[o] = __shfl_sync(0xffffffffu, v, 0, 4);
            ow1[o] = __shfl_sync(0xffffffffu, v, 1, 4);
            ow2[o] = __shfl_sync(0xffffffffu, v, 2, 4);
            ow3[o] = __shfl_sync(0xffffffffu, v, 3, 4);
        }
        ulonglong2* o2 = (ulonglong2*)(((float4*)out) + r0 * 128);
        #pragma unroll
        for (int jj = 0; jj < 4; jj++) {
            int j = jj*32 + lane;
            ull A0[2] = {0ull,0ull}, A1[2] = {0ull,0ull};
            ull A2[2] = {0ull,0ull}, A3[2] = {0ull,0ull};
            #pragma unroll
            for (int o = 0; o < 16; o++) {
                ulonglong2 kk = ((const ulonglong2*)op4)[o*128 + j];
                ull d0 = dup2(ow0[o]), d1 = dup2(ow1[o]);
                ull d2 = dup2(ow2[o]), d3 = dup2(ow3[o]);
                A0[0] = ffma2(d0, kk.x, A0[0]); A0[1] = ffma2(d0, kk.y, A0[1]);
                A1[0] = ffma2(d1, kk.x, A1[0]); A1[1] = ffma2(d1, kk.y, A1[1]);
                A2[0] = ffma2(d2, kk.x, A2[0]); A2[1] = ffma2(d2, kk.y, A2[1]);
                A3[0] = ffma2(d3, kk.x, A3[0]); A3[1] = ffma2(d3, kk.y, A3[1]);
            }
            o2[j]        = make_ulonglong2(A0[0], A0[1]);
            o2[128 + j]  = make_ulonglong2(A1[0], A1[1]);
            o2[256 + j]  = make_ulonglong2(A2[0], A2[1]);
            o2[384 + j]  = make_ulonglong2(A3[0], A3[1]);
        }
    }
}

// ---------------------------------------------------------------------------
extern "C" void kernel_launch(void* const* d_in, const int* in_sizes, int n_in,
                              void* d_out, int out_size) {
    const float* x     = (const float*)d_in[0];
    const float* Wv    = (const float*)d_in[1];
    const float* bv    = (const float*)d_in[2];
    const float* Wk    = (const float*)d_in[3];
    const float* bk    = (const float*)d_in[4];
    const float* Wq_op = (const float*)d_in[5];
    const float* bq_op = (const float*)d_in[6];
    const float* ops   = (const float*)d_in[7];
    (void)in_sizes; (void)n_in;
    float* out = (float*)d_out;
    float* oq_out = (out_size >= Bq*Sq*Hq + Oq*Hq) ? out + (size_t)Bq*Sq*Hq : nullptr;

    kzero<<<512, 256>>>();
    k0a<<<dim3(8, 16), 512>>>(Wq_op, ops);
    k0b<<<dim3(16, 4), 128>>>(Wk, bk, bq_op, oq_out);
    kA<<<1024, 256>>>(x, ops);
    k3<<<dim3(16, 16), 128>>>(Wv, bv);
    k4<<<dim3(32, 16), 256>>>(out);
}

// round 4
// speedup vs baseline: 1.8194x; 1.8194x over previous
#include <cuda_runtime.h>
#include <math.h>

#define Bq 16
#define Sq 2048
#define Hq 512
#define Oq 16
#define BSq (Bq*Sq)            // 32768
#define RSQRT_H 0.04419417382415922f   // 1/sqrt(512)

typedef unsigned long long ull;

__device__ __forceinline__ ull ffma2(ull a, ull b, ull c) {
    ull d; asm("fma.rn.f32x2 %0, %1, %2, %3;" : "=l"(d) : "l"(a), "l"(b), "l"(c));
    return d;
}
__device__ __forceinline__ ull dup2(float f) {
    ull r; asm("mov.b64 %0, {%1, %1};" : "=l"(r) : "f"(f));
    return r;
}

// ---------------- scratch (device globals) ----------------------------------
__device__ float g_oq[Oq*Hq];              // raw operator queries (atomic accum)
__device__ float g_kq[Oq*Hq];              // oq @ Wk, pre-scaled  [o][k]
__device__ float g_c[Oq];                  // bk . oq, pre-scaled
__device__ float g_logits[BSq*Oq];         // [b][s][o]
__device__ float g_esum[Bq*Oq];            // sum_s exp(logits)  (atomic)
__device__ float g_W[Bq*Oq];               // sum_s w (normalized, atomic)
__device__ float g_up[16*Bq*Oq*Hq];        // split-s partials of u (normalized)
__device__ float g_u[Bq*Oq*Hq];            // sum_s w * x (normalized)
__device__ float g_opout[Bq*Oq*Hq];        // operator outputs

// ---------------- K-zero -----------------------------------------------------
__global__ void kzero() {
    int i = blockIdx.x * 256 + threadIdx.x;
    if (i < Oq*Hq) g_oq[i] = 0.f;
    if (i < Bq*Oq) { g_esum[i] = 0.f; g_W[i] = 0.f; }
}

// ---------------- K0a: oq[o][h] = sum_s ops[s][o] * Wq_op[h][s] --------------
__global__ void __launch_bounds__(512) k0a(const float* __restrict__ Wq_op,
                                           const float* __restrict__ ops) {
    __shared__ float ops_sh[128*16];
    __shared__ float wq_sh[64][129];
    int h0 = blockIdx.x * 64, s0 = blockIdx.y * 128;
    for (int i = threadIdx.x; i < 128*16; i += 512)
        ops_sh[i] = ops[s0*16 + i];
    for (int i = threadIdx.x; i < 64*128; i += 512) {
        int r = i >> 7, c = i & 127;
        wq_sh[r][c] = Wq_op[(size_t)(h0 + r)*Sq + s0 + c];
    }
    __syncthreads();
    int hl = threadIdx.x & 63;
    int og = threadIdx.x >> 6;
    float a0 = 0.f, a1 = 0.f;
    #pragma unroll 8
    for (int s = 0; s < 128; s++) {
        float wv = wq_sh[hl][s];
        a0 += wv * ops_sh[s*16 + og*2];
        a1 += wv * ops_sh[s*16 + og*2 + 1];
    }
    atomicAdd(&g_oq[(og*2    )*Hq + h0 + hl], a0);
    atomicAdd(&g_oq[(og*2 + 1)*Hq + h0 + hl], a1);
}

// ---------------- K0b: kq[o][k] = (oq+bq)@Wk * rs; c = bk.(oq+bq)*rs ---------
// grid (16 o, 16 kc of 32 cols), 128 threads: h split 4-way for MLP
__global__ void __launch_bounds__(128) k0b(const float* __restrict__ Wk,
                                           const float* __restrict__ bk,
                                           const float* __restrict__ bq,
                                           float* oq_out) {
    __shared__ float oq_sh[Hq];
    __shared__ float red[4][33];
    __shared__ float cr[128];
    int o = blockIdx.x, kc = blockIdx.y;
    for (int h = threadIdx.x; h < Hq; h += 128) {
        float v = g_oq[o*Hq + h] + bq[h];
        oq_sh[h] = v;
        if (kc == 0 && oq_out) oq_out[o*Hq + h] = v;
    }
    __syncthreads();
    int kl = threadIdx.x & 31, hq = threadIdx.x >> 5;
    int k = kc*32 + kl;
    const float* wp = Wk + (size_t)(hq*128)*Hq + k;
    float a = 0.f;
    #pragma unroll 16
    for (int h = 0; h < 128; h++)
        a += oq_sh[hq*128 + h] * wp[(size_t)h*Hq];
    red[hq][kl] = a;
    __syncthreads();
    if (hq == 0)
        g_kq[o*Hq + k] = (red[0][kl] + red[1][kl] + red[2][kl] + red[3][kl]) * RSQRT_H;
    if (kc == 0) {
        float cl = 0.f;
        for (int h = threadIdx.x; h < Hq; h += 128) cl += bk[h] * oq_sh[h];
        cr[threadIdx.x] = cl;
        __syncthreads();
        for (int st = 64; st > 0; st >>= 1) {
            if (threadIdx.x < st) cr[threadIdx.x] += cr[threadIdx.x + st];
            __syncthreads();
        }
        if (threadIdx.x == 0) g_c[o] = cr[0] * RSQRT_H;
    }
}

// ---------------- K1: logits[b,s,o] = x[b,s,:].kq[o,:] + c[o]; fused esum ---
// (round-2 version, conflict-free) grid 1024, 256 threads
__global__ void __launch_bounds__(256) k1(const float* __restrict__ x) {
    __shared__ float4 kq4[Oq*128];
    __shared__ float c_sh[Oq];
    __shared__ float st[32*16];
    __shared__ float esr[16][17];
    for (int i = threadIdx.x; i < Oq*128; i += 256)
        kq4[i] = ((const float4*)g_kq)[i];
    if (threadIdx.x < Oq) c_sh[threadIdx.x] = g_c[threadIdx.x];
    __syncthreads();
    int wid = threadIdx.x >> 5, lane = threadIdx.x & 31;
    int r0 = blockIdx.x * 32 + wid * 4;
    const float4* xr = ((const float4*)x) + (size_t)r0 * 128;
    float acc[4][16];
    #pragma unroll
    for (int r = 0; r < 4; r++)
        #pragma unroll
        for (int o = 0; o < 16; o++) acc[r][o] = 0.f;
    #pragma unroll
    for (int jj = 0; jj < 4; jj++) {
        int j = jj * 32 + lane;
        float4 x0 = xr[j], x1 = xr[128 + j], x2 = xr[256 + j], x3 = xr[384 + j];
        #pragma unroll
        for (int o = 0; o < 16; o++) {
            float4 kv = kq4[o*128 + j];
            acc[0][o] += x0.x*kv.x + x0.y*kv.y + x0.z*kv.z + x0.w*kv.w;
            acc[1][o] += x1.x*kv.x + x1.y*kv.y + x1.z*kv.z + x1.w*kv.w;
            acc[2][o] += x2.x*kv.x + x2.y*kv.y + x2.z*kv.z + x2.w*kv.w;
            acc[3][o] += x3.x*kv.x + x3.y*kv.y + x3.z*kv.z + x3.w*kv.w;
        }
    }
    #pragma unroll
    for (int r = 0; r < 4; r++)
        #pragma unroll
        for (int o = 0; o < 16; o++) {
            float v = acc[r][o];
            v += __shfl_down_sync(0xffffffffu, v, 16);
            v += __shfl_down_sync(0xffffffffu, v, 8);
            v += __shfl_down_sync(0xffffffffu, v, 4);
            v += __shfl_down_sync(0xffffffffu, v, 2);
            v += __shfl_down_sync(0xffffffffu, v, 1);
            acc[r][o] = v;
        }
    if (lane == 0) {
        #pragma unroll
        for (int r = 0; r < 4; r++)
            #pragma unroll
            for (int o = 0; o < 16; o++)
                st[(wid*4 + r)*16 + o] = acc[r][o] + c_sh[o];
    }
    __syncthreads();
    float v0 = st[threadIdx.x];
    float v1 = st[threadIdx.x + 256];
    size_t gbase = (size_t)blockIdx.x * 512;
    g_logits[gbase + threadIdx.x]       = v0;
    g_logits[gbase + threadIdx.x + 256] = v1;
    float ep = __expf(v0) + __expf(v1);
    esr[threadIdx.x >> 4][threadIdx.x & 15] = ep;
    __syncthreads();
    if (threadIdx.x < 16) {
        float s = 0.f;
        #pragma unroll
        for (int j = 0; j < 16; j++) s += esr[j][threadIdx.x];
        int b = blockIdx.x >> 6;
        atomicAdd(&g_esum[b*16 + threadIdx.x], s);
    }
}

// ---------------- K2: split-s partials of u = sum_s w*x (w normalized) ------
// grid (16 sc, 16 b), 256 threads; thread owns k=tid, tid+256; 128 s per block
__global__ void __launch_bounds__(256) k2(const float* __restrict__ x,
                                          const float* __restrict__ ops) {
    __shared__ __align__(16) float w_sh[128*16];   // 8KB
    __shared__ float inv_sh[16];
    __shared__ float wr[16][17];
    int sc = blockIdx.x, b = blockIdx.y;
    int tid = threadIdx.x;
    int s0 = sc * 128;
    if (tid < 16) inv_sh[tid] = 1.0f / g_esum[b*16 + tid];
    __syncthreads();
    const float* L  = g_logits + ((size_t)b*Sq + s0)*16;
    const float* op = ops + (size_t)s0*16;
    float Wloc = 0.f;
    #pragma unroll
    for (int t = 0; t < 8; t++) {
        int i = t*256 + tid;
        float wv = __expf(L[i]) * inv_sh[i & 15] * op[i];
        w_sh[i] = wv;
        Wloc += wv;
    }
    wr[tid >> 4][tid & 15] = Wloc;
    __syncthreads();
    if (tid < 16) {
        float s = 0.f;
        #pragma unroll
        for (int j = 0; j < 16; j++) s += wr[j][tid];
        atomicAdd(&g_W[b*16 + tid], s);
    }
    const float* xq = x + ((size_t)b*Sq + s0)*Hq + tid;
    ull a0[8], a1[8];
    #pragma unroll
    for (int j = 0; j < 8; j++) { a0[j] = 0ull; a1[j] = 0ull; }
    #pragma unroll 8
    for (int s = 0; s < 128; s++) {
        float xv0 = xq[(size_t)s*Hq];
        float xv1 = xq[(size_t)s*Hq + 256];
        ull xa = dup2(xv0), xb = dup2(xv1);
        const ull* w8 = (const ull*)(w_sh + s*16);
        #pragma unroll
        for (int j = 0; j < 8; j++) {
            ull wv = w8[j];
            a0[j] = ffma2(xa, wv, a0[j]);
            a1[j] = ffma2(xb, wv, a1[j]);
        }
    }
    float* up = g_up + (size_t)(sc*16 + b)*16*512;
    #pragma unroll
    for (int j = 0; j < 8; j++) {
        float lo, hi;
        asm("mov.b64 {%0,%1}, %2;" : "=f"(lo), "=f"(hi) : "l"(a0[j]));
        up[(2*j)*512 + tid]         = lo;
        up[(2*j+1)*512 + tid]       = hi;
        asm("mov.b64 {%0,%1}, %2;" : "=f"(lo), "=f"(hi) : "l"(a1[j]));
        up[(2*j)*512 + tid + 256]   = lo;
        up[(2*j+1)*512 + tid + 256] = hi;
    }
}

// ---------------- Ksum: u = sum of 16 split-s partials -----------------------
// g_up layout: [(sc*16 + b)][8192 floats]; output g_u[b][8192]
__global__ void ksum() {
    int i = blockIdx.x*256 + threadIdx.x;   // 32768 float4s
    int b = i >> 11, w4 = i & 2047;
    const float4* up4 = (const float4*)g_up;
    float4 s = up4[(size_t)b*2048 + w4];
    #pragma unroll
    for (int p = 1; p < 16; p++) {
        float4 t = up4[(size_t)(p*16 + b)*2048 + w4];
        s.x += t.x; s.y += t.y; s.z += t.z; s.w += t.w;
    }
    ((float4*)g_u)[i] = s;
}

// fold-reduce 16 floats over 32 lanes; lane l (<16) ends holding total of v[l]
__device__ __forceinline__ float fold16(float v[16], int lane) {
    #pragma unroll
    for (int i = 0; i < 16; i++)
        v[i] += __shfl_xor_sync(0xffffffffu, v[i], 16);
    #pragma unroll
    for (int i = 0; i < 8; i++) {
        float mn = (lane & 8) ? v[i+8] : v[i];
        float th = (lane & 8) ? v[i] : v[i+8];
        v[i] = mn + __shfl_xor_sync(0xffffffffu, th, 8);
    }
    #pragma unroll
    for (int i = 0; i < 4; i++) {
        float mn = (lane & 4) ? v[i+4] : v[i];
        float th = (lane & 4) ? v[i] : v[i+4];
        v[i] = mn + __shfl_xor_sync(0xffffffffu, th, 4);
    }
    #pragma unroll
    for (int i = 0; i < 2; i++) {
        float mn = (lane & 2) ? v[i+2] : v[i];
        float th = (lane & 2) ? v[i] : v[i+2];
        v[i] = mn + __shfl_xor_sync(0xffffffffu, th, 2);
    }
    {
        float mn = (lane & 1) ? v[1] : v[0];
        float th = (lane & 1) ? v[0] : v[1];
        v[0] = mn + __shfl_xor_sync(0xffffffffu, th, 1);
    }
    return v[0];
}

// ---------------- K3: op_out[b,o,h] = u[b,o,:].Wv[h,:] + bv[h]*W[b,o] -------
// grid (16 o, 8 hc of 64), 256 threads (8 warps)
__global__ void __launch_bounds__(256) k3(const float* __restrict__ Wv,
                                          const float* __restrict__ bv) {
    __shared__ float4 u4[16*128];
    __shared__ float Wsh[16];
    int o = blockIdx.x, hc = blockIdx.y;
    for (int i = threadIdx.x; i < 16*128; i += 256) {
        int b = i >> 7, k4 = i & 127;
        u4[i] = ((const float4*)g_u)[((size_t)b*16 + o)*128 + k4];
    }
    if (threadIdx.x < 16) Wsh[threadIdx.x] = g_W[threadIdx.x*16 + o];
    __syncthreads();
    int wid = threadIdx.x >> 5, lane = threadIdx.x & 31;
    for (int q = 0; q < 2; q++) {
        int h = hc*64 + wid*8 + q*4;
        const float4* wv = ((const float4*)Wv) + (size_t)h * 128;
        float acc[4][16];
        #pragma unroll
        for (int r = 0; r < 4; r++)
            #pragma unroll
            for (int b = 0; b < 16; b++) acc[r][b] = 0.f;
        #pragma unroll
        for (int jj = 0; jj < 4; jj++) {
            int j = jj*32 + lane;
            float4 v0 = wv[j], v1 = wv[128+j], v2 = wv[256+j], v3 = wv[384+j];
            #pragma unroll
            for (int b = 0; b < 16; b++) {
                float4 uu = u4[b*128 + j];
                acc[0][b] += v0.x*uu.x + v0.y*uu.y + v0.z*uu.z + v0.w*uu.w;
                acc[1][b] += v1.x*uu.x + v1.y*uu.y + v1.z*uu.z + v1.w*uu.w;
                acc[2][b] += v2.x*uu.x + v2.y*uu.y + v2.z*uu.z + v2.w*uu.w;
                acc[3][b] += v3.x*uu.x + v3.y*uu.y + v3.z*uu.z + v3.w*uu.w;
            }
        }
        #pragma unroll
        for (int r = 0; r < 4; r++) {
            float t = fold16(acc[r], lane);
            if (lane < 16)
                g_opout[((size_t)lane*16 + o)*Hq + h + r] = t + bv[h + r] * Wsh[lane];
        }
    }
}

// ---------------- K4: out[b,s,h] = sum_o softmax_o(L)[o]*op_out[b,o,h] ------
__global__ void __launch_bounds__(256) k4(float* __restrict__ out) {
    __shared__ __align__(16) float4 op4[16*128];
    int b = blockIdx.y, sc = blockIdx.x;
    for (int i = threadIdx.x; i < 16*128; i += 256)
        op4[i] = ((const float4*)g_opout)[(size_t)b*2048 + i];
    __syncthreads();
    int wid = threadIdx.x >> 5, lane = threadIdx.x & 31;
    for (int q = 0; q < 2; q++) {
        int s0 = sc*64 + wid*8 + q*4;
        size_t r0 = (size_t)b*Sq + s0;
        const float* lp = g_logits + (r0 + (lane & 3)) * 16;
        float e[16];
        float mx = -1e30f;
        #pragma unroll
        for (int o = 0; o < 16; o++) { e[o] = lp[o]; mx = fmaxf(mx, e[o]); }
        float sum = 0.f;
        #pragma unroll
        for (int o = 0; o < 16; o++) { e[o] = __expf(e[o] - mx); sum += e[o]; }
        float inv = 1.0f / sum;
        float ow0[16], ow1[16], ow2[16], ow3[16];
        #pragma unroll
        for (int o = 0; o < 16; o++) {
            float v = e[o] * inv;
            ow0[o] = __shfl_sync(0xffffffffu, v, 0, 4);
            ow1[o] = __shfl_sync(0xffffffffu, v, 1, 4);
            ow2[o] = __shfl_sync(0xffffffffu, v, 2, 4);
            ow3[o] = __shfl_sync(0xffffffffu, v, 3, 4);
        }
        ulonglong2* o2 = (ulonglong2*)(((float4*)out) + r0 * 128);
        #pragma unroll
        for (int jj = 0; jj < 4; jj++) {
            int j = jj*32 + lane;
            ull A0[2] = {0ull,0ull}, A1[2] = {0ull,0ull};
            ull A2[2] = {0ull,0ull}, A3[2] = {0ull,0ull};
            #pragma unroll
            for (int o = 0; o < 16; o++) {
                ulonglong2 kk = ((const ulonglong2*)op4)[o*128 + j];
                ull d0 = dup2(ow0[o]), d1 = dup2(ow1[o]);
                ull d2 = dup2(ow2[o]), d3 = dup2(ow3[o]);
                A0[0] = ffma2(d0, kk.x, A0[0]); A0[1] = ffma2(d0, kk.y, A0[1]);
                A1[0] = ffma2(d1, kk.x, A1[0]); A1[1] = ffma2(d1, kk.y, A1[1]);
                A2[0] = ffma2(d2, kk.x, A2[0]); A2[1] = ffma2(d2, kk.y, A2[1]);
                A3[0] = ffma2(d3, kk.x, A3[0]); A3[1] = ffma2(d3, kk.y, A3[1]);
            }
            o2[j]        = make_ulonglong2(A0[0], A0[1]);
            o2[128 + j]  = make_ulonglong2(A1[0], A1[1]);
            o2[256 + j]  = make_ulonglong2(A2[0], A2[1]);
            o2[384 + j]  = make_ulonglong2(A3[0], A3[1]);
        }
    }
}

// ---------------------------------------------------------------------------
extern "C" void kernel_launch(void* const* d_in, const int* in_sizes, int n_in,
                              void* d_out, int out_size) {
    const float* x     = (const float*)d_in[0];
    const float* Wv    = (const float*)d_in[1];
    const float* bv    = (const float*)d_in[2];
    const float* Wk    = (const float*)d_in[3];
    const float* bk    = (const float*)d_in[4];
    const float* Wq_op = (const float*)d_in[5];
    const float* bq_op = (const float*)d_in[6];
    const float* ops   = (const float*)d_in[7];
    (void)in_sizes; (void)n_in;
    float* out = (float*)d_out;
    float* oq_out = (out_size >= Bq*Sq*Hq + Oq*Hq) ? out + (size_t)Bq*Sq*Hq : nullptr;

    kzero<<<32, 256>>>();
    k0a<<<dim3(8, 16), 512>>>(Wq_op, ops);
    k0b<<<dim3(16, 16), 128>>>(Wk, bk, bq_op, oq_out);
    k1<<<BSq/32, 256>>>(x);
    k2<<<dim3(16, 16), 256>>>(x, ops);
    ksum<<<128, 256>>>();
    k3<<<dim3(16, 8), 256>>>(Wv, bv);
    k4<<<dim3(32, 16), 256>>>(out);
}